// round 10
// baseline (speedup 1.0000x reference)
#include <cuda_runtime.h>
#include <cuda_bf16.h>
#include <cstdint>

// Problem constants
#define NB 16
#define SS 4096
#define NTOK (NB*SS)        // 65536
#define EE 128
#define DM 64
#define NH 8
#define DH 8
#define FFD 256
#define CC 1623
#define NL 8
#define NCHUNK 32           // kv partial chunks per batch (= SS/128)

// Scratch (device globals — allocation-free per harness rules)
__device__ float g_hh[NTOK*DM];
__device__ float g_pq[NTOK*DM];
__device__ float g_kvp[NB*NH*NCHUNK*72];
__device__ float g_kv[NB*NH*DH*DH];
__device__ float g_ks[NB*NH*DH];

__device__ __forceinline__ float phi_f(float x) {
    return x > 0.f ? x + 1.f : __expf(x);   // elu(x)+1
}

__device__ __forceinline__ float gelu_f(float x) {
    float x3 = x * x * x;
    return 0.5f * x * (1.f + tanhf(0.7978845608028654f * (x + 0.044715f * x3)));
}

// ===================== packed f32x2 helpers =====================
__device__ __forceinline__ uint64_t pack2(float x, float y) {
    uint64_t r; asm("mov.b64 %0, {%1, %2};" : "=l"(r) : "f"(x), "f"(y)); return r;
}
__device__ __forceinline__ void unpack2(uint64_t v, float& x, float& y) {
    asm("mov.b64 {%0, %1}, %2;" : "=f"(x), "=f"(y) : "l"(v));
}
__device__ __forceinline__ void ffma2(uint64_t& d, uint64_t a, uint64_t b) {
    asm("fma.rn.f32x2 %0, %1, %2, %3;" : "=l"(d) : "l"(a), "l"(b), "l"(d));
}

// ---- packed register-tiled GEMM fragments: A transposed in smem [k][tok] (pitch PA),
// ---- W in smem [k][col] (pitch PW). acc[i][j] holds output cols (c0+2j, c0+2j+1).
template<int K, int PA, int PW>
__device__ __forceinline__ void gemm_48p(const float* __restrict__ AT,
                                         const float* __restrict__ Ws,
                                         int r0, int c0, uint64_t (&acc)[4][4]) {
    #pragma unroll 8
    for (int k = 0; k < K; k++) {
        float4 a = *(const float4*)(AT + k*PA + r0);
        ulonglong2 w01 = *(const ulonglong2*)(Ws + k*PW + c0);
        ulonglong2 w23 = *(const ulonglong2*)(Ws + k*PW + c0 + 4);
        uint64_t av[4] = {pack2(a.x,a.x), pack2(a.y,a.y), pack2(a.z,a.z), pack2(a.w,a.w)};
        uint64_t wv[4] = {w01.x, w01.y, w23.x, w23.y};
        #pragma unroll
        for (int i = 0; i < 4; i++)
            #pragma unroll
            for (int j = 0; j < 4; j++)
                ffma2(acc[i][j], av[i], wv[j]);
    }
}

template<int K, int PA, int PW>
__device__ __forceinline__ void gemm_44p(const float* __restrict__ AT,
                                         const float* __restrict__ Ws,
                                         int r0, int c0, uint64_t (&acc)[4][2]) {
    #pragma unroll 8
    for (int k = 0; k < K; k++) {
        float4 a = *(const float4*)(AT + k*PA + r0);
        ulonglong2 w01 = *(const ulonglong2*)(Ws + k*PW + c0);
        uint64_t av[4] = {pack2(a.x,a.x), pack2(a.y,a.y), pack2(a.z,a.z), pack2(a.w,a.w)};
        #pragma unroll
        for (int i = 0; i < 4; i++) {
            ffma2(acc[i][0], av[i], w01.x);
            ffma2(acc[i][1], av[i], w01.y);
        }
    }
}

// ================= Kernel 0: embedding =================
// hh = (ex@we + be + lemb[labels]) @ w_in + b_in ; 64 tokens/block
__global__ __launch_bounds__(256) void k_embed(
    const float* __restrict__ ex, const int* __restrict__ labels,
    const float* __restrict__ we, const float* __restrict__ be,
    const float* __restrict__ lemb, const float* __restrict__ w_in,
    const float* __restrict__ b_in)
{
    extern __shared__ float sm[];
    float* s_eT = sm;                // [128][68]  ex^T
    float* s_tT = sm + 128*68;       // [128][68]  tmp^T
    float* s_w  = sm + 2*128*68;     // max 128*128
    float* s_c  = s_w + 128*128;     // be(128) + b_in(64)
    const int tid = threadIdx.x;
    const int t0 = blockIdx.x * 64;

    for (int i = tid; i < 192; i += 256)
        s_c[i] = (i < 128) ? be[i] : b_in[i-128];
    for (int i = tid; i < 64*EE; i += 256) {
        int r = i >> 7, c = i & 127;
        s_eT[c*68 + r] = ex[(size_t)(t0+r)*EE + c];
    }
    for (int i = tid; i < EE*EE; i += 256) s_w[i] = we[i];
    __syncthreads();

    // stage A: tmp^T = (ex@we + be + lemb)^T
    {
        int rg = tid & 15, cg = tid >> 4;
        int r0 = rg*4, c0 = cg*8;
        uint64_t acc[4][4];
        #pragma unroll
        for (int j = 0; j < 4; j++) { uint64_t b = pack2(s_c[c0+2*j], s_c[c0+2*j+1]);
            #pragma unroll
            for (int i = 0; i < 4; i++) acc[i][j] = b; }
        gemm_48p<EE,68,EE>(s_eT, s_w, r0, c0, acc);
        #pragma unroll
        for (int i = 0; i < 4; i++) {
            int lab = labels[t0 + r0 + i];
            const float* le = lemb + (size_t)lab*EE + c0;
            #pragma unroll
            for (int j = 0; j < 4; j++) {
                float o0, o1; unpack2(acc[i][j], o0, o1);
                s_tT[(c0+2*j  )*68 + r0+i] = o0 + le[2*j];
                s_tT[(c0+2*j+1)*68 + r0+i] = o1 + le[2*j+1];
            }
        }
    }
    __syncthreads();
    for (int i = tid; i < EE*DM; i += 256) s_w[i] = w_in[i];
    __syncthreads();

    // stage B: hh = tmp@w_in + b_in
    {
        int rg = tid & 15, cg = tid >> 4;
        int r0 = rg*4, c0 = cg*4;
        uint64_t acc[4][2];
        #pragma unroll
        for (int j = 0; j < 2; j++) { uint64_t b = pack2(s_c[128+c0+2*j], s_c[128+c0+2*j+1]);
            #pragma unroll
            for (int i = 0; i < 4; i++) acc[i][j] = b; }
        gemm_44p<EE,68,DM>(s_tT, s_w, r0, c0, acc);
        #pragma unroll
        for (int i = 0; i < 4; i++) {
            float o0,o1,o2,o3;
            unpack2(acc[i][0], o0, o1);
            unpack2(acc[i][1], o2, o3);
            *(float4*)(g_hh + (size_t)(t0+r0+i)*DM + c0) = make_float4(o0,o1,o2,o3);
        }
    }
}

// ================= Kernel 1: mask + LN1 + QKV (+phi) + fused kv partial reduction =================
// 128 tokens/block, 256 threads, smem ~102 KB -> 2 blocks/SM
__global__ __launch_bounds__(256, 2) void k_qkv(
    const float* __restrict__ mask,
    const float* __restrict__ ls, const float* __restrict__ lb,
    const float* __restrict__ wq, const float* __restrict__ bq,
    const float* __restrict__ wk, const float* __restrict__ bk,
    const float* __restrict__ wv, const float* __restrict__ bv)
{
    extern __shared__ float sm[];
    float* s_xT = sm;                 // [64][128]   8192
    float* s_pk = sm + 8192;          // [128][68]   8704 (phi(k)*mask, padded pitch)
    float* s_w  = sm + 8192 + 8704;   // [64][128]   8192 staging (q|k then v)
    float* s_c  = s_w + 8192;         // 320: ls|lb|bq|bk|bv
    const int tid = threadIdx.x;
    const int t0 = blockIdx.x * 128;

    for (int i = tid; i < 320; i += 256) {
        float v;
        if      (i < 64)  v = ls[i];
        else if (i < 128) v = lb[i-64];
        else if (i < 192) v = bq[i-128];
        else if (i < 256) v = bk[i-192];
        else              v = bv[i-256];
        s_c[i] = v;
    }
    // stage [wq|wk]
    for (int i = tid; i < 64*128; i += 256) {
        int k = i >> 7, c = i & 127;
        s_w[i] = (c < 64) ? wq[k*DM + c] : wk[k*DM + (c-64)];
    }

    // LN in registers (2 threads / row, 32 cols each)
    const int r = tid >> 1, g = tid & 1;
    const int n = t0 + r;
    float m = mask[n];
    float4 vv[8];
    {
        const float4* src = (const float4*)(g_hh + (size_t)n*DM + g*32);
        #pragma unroll
        for (int q = 0; q < 8; q++) {
            float4 v = src[q];
            v.x*=m; v.y*=m; v.z*=m; v.w*=m;
            vv[q] = v;
        }
        float4* dst = (float4*)(g_hh + (size_t)n*DM + g*32);
        #pragma unroll
        for (int q = 0; q < 8; q++) dst[q] = vv[q];   // hh *= mask (residual base)
    }
    float sum = 0.f, sq = 0.f;
    #pragma unroll
    for (int q = 0; q < 8; q++) {
        sum += vv[q].x+vv[q].y+vv[q].z+vv[q].w;
        sq  += vv[q].x*vv[q].x+vv[q].y*vv[q].y+vv[q].z*vv[q].z+vv[q].w*vv[q].w;
    }
    sum += __shfl_xor_sync(0xffffffffu, sum, 1);
    sq  += __shfl_xor_sync(0xffffffffu, sq , 1);
    float mean = sum * (1.f/64.f);
    float rstd = rsqrtf(sq * (1.f/64.f) - mean*mean + 1e-5f);
    __syncthreads();     // consts + weight staging done

    #pragma unroll
    for (int q = 0; q < 8; q++) {
        float vals[4] = {vv[q].x,vv[q].y,vv[q].z,vv[q].w};
        #pragma unroll
        for (int j = 0; j < 4; j++) {
            int c = g*32 + q*4 + j;
            s_xT[c*128 + r] = (vals[j]-mean)*rstd*s_c[c] + s_c[64+c];
        }
    }
    __syncthreads();

    // ---- pass A: q|k (128 cols), 512 tiles of 4x8, 2/thread ----
    for (int t = tid; t < 512; t += 256) {
        int rg = t & 31, cg = t >> 5;
        int r0 = rg*4, c0 = cg*8;
        uint64_t acc[4][4];
        #pragma unroll
        for (int j = 0; j < 4; j++) { uint64_t b = pack2(s_c[128+c0+2*j], s_c[128+c0+2*j+1]);
            #pragma unroll
            for (int i = 0; i < 4; i++) acc[i][j] = b; }
        gemm_48p<64,128,128>(s_xT, s_w, r0, c0, acc);
        #pragma unroll
        for (int i = 0; i < 4; i++) {
            int nn = t0 + r0 + i;
            float o[8];
            unpack2(acc[i][0], o[0], o[1]);
            unpack2(acc[i][1], o[2], o[3]);
            unpack2(acc[i][2], o[4], o[5]);
            unpack2(acc[i][3], o[6], o[7]);
            if (c0 < 64) {      // q -> phi -> global (k_att reads it)
                float4 o0 = make_float4(phi_f(o[0]),phi_f(o[1]),phi_f(o[2]),phi_f(o[3]));
                float4 o1 = make_float4(phi_f(o[4]),phi_f(o[5]),phi_f(o[6]),phi_f(o[7]));
                *(float4*)(g_pq + (size_t)nn*DM + c0)     = o0;
                *(float4*)(g_pq + (size_t)nn*DM + c0 + 4) = o1;
            } else {            // k -> phi*mask -> smem only
                int cc = c0 - 64;
                float mm = mask[nn];
                float4 o0 = make_float4(phi_f(o[0])*mm,phi_f(o[1])*mm,phi_f(o[2])*mm,phi_f(o[3])*mm);
                float4 o1 = make_float4(phi_f(o[4])*mm,phi_f(o[5])*mm,phi_f(o[6])*mm,phi_f(o[7])*mm);
                *(float4*)(s_pk + (r0+i)*68 + cc)     = o0;
                *(float4*)(s_pk + (r0+i)*68 + cc + 4) = o1;
            }
        }
    }
    __syncthreads();
    // ---- stage wv ----
    for (int i = tid; i < 64*64; i += 256) s_w[i] = wv[i];
    __syncthreads();

    // ---- pass B: v (64 cols), 256 tiles, 1/thread; warp w == head w ----
    const int rg = tid & 31, cg = tid >> 5;       // cg = warp = head
    const int r0 = rg*4, c0 = cg*8;
    uint64_t acc[4][4];
    #pragma unroll
    for (int j = 0; j < 4; j++) { uint64_t b = pack2(s_c[256+c0+2*j], s_c[256+c0+2*j+1]);
        #pragma unroll
        for (int i = 0; i < 4; i++) acc[i][j] = b; }
    gemm_48p<64,128,64>(s_xT, s_w, r0, c0, acc);
    float vreg[4][8];
    #pragma unroll
    for (int i = 0; i < 4; i++) {
        unpack2(acc[i][0], vreg[i][0], vreg[i][1]);
        unpack2(acc[i][1], vreg[i][2], vreg[i][3]);
        unpack2(acc[i][2], vreg[i][4], vreg[i][5]);
        unpack2(acc[i][3], vreg[i][6], vreg[i][7]);
    }
    // note: v is not needed globally (only pq + kv state leave this kernel)
    __syncthreads();   // ensure s_pk fully written (already synced above; keep for pass-B tile safety)

    // ---- fused kv partial reduction: warp h covers head h, lane covers tokens 4*lane..+3 ----
    const int bb = blockIdx.x >> 5;        // batch
    const int chunk = blockIdx.x & 31;
    const int h = cg;
    float* dst = g_kvp + ((size_t)((bb*NH + h)*NCHUNK + chunk))*72;
    #pragma unroll
    for (int dh = 0; dh < 2; dh++) {
        float kvh[4][8] = {};
        float ksh[4] = {};
        #pragma unroll
        for (int i2 = 0; i2 < 4; i2++) {
            int t = r0 + i2;
            float4 p = *(const float4*)(s_pk + t*68 + h*8 + dh*4);
            float pd[4] = {p.x, p.y, p.z, p.w};
            #pragma unroll
            for (int d = 0; d < 4; d++) {
                ksh[d] += pd[d];
                #pragma unroll
                for (int e = 0; e < 8; e++) kvh[d][e] += pd[d]*vreg[i2][e];
            }
        }
        #pragma unroll
        for (int o = 16; o > 0; o >>= 1) {
            #pragma unroll
            for (int d = 0; d < 4; d++) {
                ksh[d] += __shfl_down_sync(0xffffffffu, ksh[d], o);
                #pragma unroll
                for (int e = 0; e < 8; e++)
                    kvh[d][e] += __shfl_down_sync(0xffffffffu, kvh[d][e], o);
            }
        }
        if (rg == 0) {
            #pragma unroll
            for (int d = 0; d < 4; d++) {
                #pragma unroll
                for (int e = 0; e < 8; e++) dst[(dh*4+d)*8 + e] = kvh[d][e];
                dst[64 + dh*4 + d] = ksh[d];
            }
        }
    }
}

// ================= Kernel 2: tiny kv chunk combine (deterministic) =================
__global__ __launch_bounds__(256) void k_kvcomb() {
    int i = blockIdx.x*256 + threadIdx.x;      // over NB*NH*72 = 9216
    if (i >= NB*NH*72) return;
    int bh = i / 72, idx = i % 72;
    float acc = 0.f;
    #pragma unroll
    for (int c = 0; c < NCHUNK; c++) acc += g_kvp[(size_t)(bh*NCHUNK + c)*72 + idx];
    if (idx < 64) g_kv[bh*64 + idx] = acc;
    else          g_ks[bh*8 + (idx-64)] = acc;
}

// ================= Kernel 3: attention readout + @wo + residual =================
// 128 tokens/block
__global__ __launch_bounds__(256) void k_att(
    const float* __restrict__ wo, const float* __restrict__ bo)
{
    extern __shared__ float sm[];
    float* s_attT = sm;               // [64][128]
    float* s_w    = sm + 64*128;      // wo [64][64]
    float* s_kv   = s_w + 64*64;      // 512
    float* s_ks   = s_kv + 512;       // 64
    float* s_bo   = s_ks + 64;        // 64
    const int tid = threadIdx.x;
    const int t0 = blockIdx.x * 128;
    const int b = t0 >> 12;           // t0 / SS

    for (int i = tid; i < 64*64; i += 256) s_w[i] = wo[i];
    for (int i = tid; i < 512; i += 256)   s_kv[i] = g_kv[b*512 + i];
    if (tid < 64)  s_ks[tid] = g_ks[b*64 + tid];
    else if (tid < 128) s_bo[tid-64] = bo[tid-64];

    const int r = tid >> 1, g = tid & 1;
    const int n = t0 + r;
    float p[32];
    {
        const float4* src = (const float4*)(g_pq + (size_t)n*DM + g*32);
        #pragma unroll
        for (int q = 0; q < 8; q++) {
            float4 v = src[q];
            p[q*4+0]=v.x; p[q*4+1]=v.y; p[q*4+2]=v.z; p[q*4+3]=v.w;
        }
    }
    __syncthreads();

    #pragma unroll
    for (int u = 0; u < 4; u++) {
        int h = g*4 + u;
        float den = 0.f;
        #pragma unroll
        for (int d = 0; d < 8; d++) den += p[u*8+d] * s_ks[h*8+d];
        float inv = 1.f / (den + 1e-6f);
        const float* kvb = s_kv + h*64;
        #pragma unroll
        for (int e = 0; e < 8; e++) {
            float num = 0.f;
            #pragma unroll
            for (int d = 0; d < 8; d++) num += p[u*8+d] * kvb[d*8+e];
            s_attT[(g*32 + u*8 + e)*128 + r] = num * inv;
        }
    }
    __syncthreads();

    // GEMM att@wo + bo, += hh ; 256 tiles (4x8), 1/thread
    {
        int rg = tid & 31, cg = tid >> 5;
        int r0 = rg*4, c0 = cg*8;
        uint64_t acc[4][4];
        #pragma unroll
        for (int j = 0; j < 4; j++) { uint64_t bb = pack2(s_bo[c0+2*j], s_bo[c0+2*j+1]);
            #pragma unroll
            for (int i = 0; i < 4; i++) acc[i][j] = bb; }
        gemm_48p<64,128,64>(s_attT, s_w, r0, c0, acc);
        #pragma unroll
        for (int i = 0; i < 4; i++) {
            float o[8];
            unpack2(acc[i][0], o[0], o[1]);
            unpack2(acc[i][1], o[2], o[3]);
            unpack2(acc[i][2], o[4], o[5]);
            unpack2(acc[i][3], o[6], o[7]);
            float4* ph = (float4*)(g_hh + (size_t)(t0+r0+i)*DM + c0);
            float4 h0 = ph[0], h1 = ph[1];
            h0.x += o[0]; h0.y += o[1]; h0.z += o[2]; h0.w += o[3];
            h1.x += o[4]; h1.y += o[5]; h1.z += o[6]; h1.w += o[7];
            ph[0] = h0; ph[1] = h1;
        }
    }
}

// ================= Kernel 4: fused LN2 + FFN(up,gelu,down) + residual =================
// 128 tokens/block, 512 threads, t1 tile in smem (198 KB)
__global__ __launch_bounds__(512, 1) void k_ffn(
    const float* __restrict__ ls, const float* __restrict__ lb,
    const float* __restrict__ w1, const float* __restrict__ b1,
    const float* __restrict__ w2, const float* __restrict__ b2)
{
    extern __shared__ float sm[];
    float* s_yT  = sm;                 // [64][128]   8192
    float* s_t1T = sm + 8192;          // [256][128]  32768
    float* s_w   = s_t1T + 32768;      // [64][128]/[128][64] staging 8192
    float* s_c   = s_w + 8192;         // ls 64 | lb 64 | b1 256 | b2 64 = 448
    const int tid = threadIdx.x;
    const int t0 = blockIdx.x * 128;

    for (int i = tid; i < 448; i += 512) {
        float v;
        if      (i < 64)  v = ls[i];
        else if (i < 128) v = lb[i-64];
        else if (i < 384) v = b1[i-128];
        else              v = b2[i-384];
        s_c[i] = v;
    }

    // LN2 in registers (4 threads / row, 16 cols each)
    const int r = tid >> 2, g = tid & 3;
    const int n = t0 + r;
    float4 vv[4];
    {
        const float4* src = (const float4*)(g_hh + (size_t)n*DM + g*16);
        #pragma unroll
        for (int q = 0; q < 4; q++) vv[q] = src[q];
    }
    float sum = 0.f, sq = 0.f;
    #pragma unroll
    for (int q = 0; q < 4; q++) {
        sum += vv[q].x+vv[q].y+vv[q].z+vv[q].w;
        sq  += vv[q].x*vv[q].x+vv[q].y*vv[q].y+vv[q].z*vv[q].z+vv[q].w*vv[q].w;
    }
    sum += __shfl_xor_sync(0xffffffffu, sum, 1);
    sq  += __shfl_xor_sync(0xffffffffu, sq , 1);
    sum += __shfl_xor_sync(0xffffffffu, sum, 2);
    sq  += __shfl_xor_sync(0xffffffffu, sq , 2);
    float mean = sum * (1.f/64.f);
    float rstd = rsqrtf(sq * (1.f/64.f) - mean*mean + 1e-5f);
    __syncthreads();   // s_c staged

    #pragma unroll
    for (int q = 0; q < 4; q++) {
        float vals[4] = {vv[q].x,vv[q].y,vv[q].z,vv[q].w};
        #pragma unroll
        for (int j = 0; j < 4; j++) {
            int c = g*16 + q*4 + j;
            s_yT[c*128 + r] = (vals[j]-mean)*rstd*s_c[c] + s_c[64+c];
        }
    }

    // FFN up: two 128-col halves; 512 tiles of 4x8 per half, 1/thread
    const int rg = tid & 31, cg = tid >> 5;    // rg 0..31, cg 0..15
    const int r0 = rg*4;
    for (int h01 = 0; h01 < 2; h01++) {
        __syncthreads();   // yT ready / prior s_w reads done
        for (int i = tid; i < 64*128; i += 512) {
            int k = i >> 7, c = i & 127;
            s_w[i] = w1[k*FFD + h01*128 + c];
        }
        __syncthreads();
        int c0 = cg*8;
        uint64_t acc[4][4];
        #pragma unroll
        for (int j = 0; j < 4; j++) { uint64_t bb = pack2(s_c[128 + h01*128 + c0+2*j], s_c[128 + h01*128 + c0+2*j+1]);
            #pragma unroll
            for (int i = 0; i < 4; i++) acc[i][j] = bb; }
        gemm_48p<64,128,128>(s_yT, s_w, r0, c0, acc);
        #pragma unroll
        for (int i = 0; i < 4; i++) {
            #pragma unroll
            for (int j = 0; j < 4; j++) {
                float o0, o1; unpack2(acc[i][j], o0, o1);
                s_t1T[(h01*128 + c0+2*j  )*128 + r0+i] = gelu_f(o0);
                s_t1T[(h01*128 + c0+2*j+1)*128 + r0+i] = gelu_f(o1);
            }
        }
    }

    // FFN down: K=256 in two halves, accumulator persists; 512 tiles of 4x4
    const int c0b = cg*4;
    uint64_t acc2[4][2];
    #pragma unroll
    for (int j = 0; j < 2; j++) { uint64_t bb = pack2(s_c[384 + c0b+2*j], s_c[384 + c0b+2*j+1]);
        #pragma unroll
        for (int i = 0; i < 4; i++) acc2[i][j] = bb; }
    for (int kh = 0; kh < 2; kh++) {
        __syncthreads();
        for (int i = tid; i < 128*64; i += 512) {
            int k = i >> 6, c = i & 63;
            s_w[i] = w2[(size_t)(kh*128 + k)*DM + c];
        }
        __syncthreads();
        gemm_44p<128,128,64>(s_t1T + kh*128*128, s_w, r0, c0b, acc2);
    }
    #pragma unroll
    for (int i = 0; i < 4; i++) {
        float o0,o1,o2,o3;
        unpack2(acc2[i][0], o0, o1);
        unpack2(acc2[i][1], o2, o3);
        float4* ph = (float4*)(g_hh + (size_t)(t0+r0+i)*DM + c0b);
        float4 h0 = *ph;
        h0.x += o0; h0.y += o1; h0.z += o2; h0.w += o3;
        *ph = h0;
    }
}

// ================= Kernel 5: final LN + mask + output GEMM =================
// 64 tokens/block x 256-col chunks
__global__ __launch_bounds__(256) void k_out(
    const float* __restrict__ mask,
    const float* __restrict__ ls, const float* __restrict__ lb,
    const float* __restrict__ w_out, const float* __restrict__ b_out,
    float* __restrict__ out)
{
    extern __shared__ float sm[];
    float* s_xT = sm;               // [64][64]
    float* s_w  = sm + 64*64;       // [64][256] chunk
    float* s_c  = s_w + 64*256;     // ls 64 | lb 64 | bias 256
    const int tid = threadIdx.x;
    const int t0 = blockIdx.x * 64;
    const int c00 = blockIdx.y * 256;

    for (int i = tid; i < 384; i += 256) {
        float v;
        if      (i < 64)  v = ls[i];
        else if (i < 128) v = lb[i-64];
        else { int c = c00 + i - 128; v = (c < CC) ? b_out[c] : 0.f; }
        s_c[i] = v;
    }
    for (int i = tid; i < 64*256; i += 256) {
        int k = i >> 8, j = i & 255;
        int c = c00 + j;
        s_w[i] = (c < CC) ? w_out[(size_t)k*CC + c] : 0.f;
    }

    // final LN (+mask) in registers
    const int r = tid >> 2, g = tid & 3;
    const int n = t0 + r;
    float4 vv[4];
    {
        const float4* src = (const float4*)(g_hh + (size_t)n*DM + g*16);
        #pragma unroll
        for (int q = 0; q < 4; q++) vv[q] = src[q];
    }
    float sum = 0.f, sq = 0.f;
    #pragma unroll
    for (int q = 0; q < 4; q++) {
        sum += vv[q].x+vv[q].y+vv[q].z+vv[q].w;
        sq  += vv[q].x*vv[q].x+vv[q].y*vv[q].y+vv[q].z*vv[q].z+vv[q].w*vv[q].w;
    }
    sum += __shfl_xor_sync(0xffffffffu, sum, 1);
    sq  += __shfl_xor_sync(0xffffffffu, sq , 1);
    sum += __shfl_xor_sync(0xffffffffu, sum, 2);
    sq  += __shfl_xor_sync(0xffffffffu, sq , 2);
    float mean = sum * (1.f/64.f);
    float rstd = rsqrtf(sq * (1.f/64.f) - mean*mean + 1e-5f);
    float m = mask[n];
    __syncthreads();

    #pragma unroll
    for (int q = 0; q < 4; q++) {
        float vals[4] = {vv[q].x,vv[q].y,vv[q].z,vv[q].w};
        #pragma unroll
        for (int j = 0; j < 4; j++) {
            int c = g*16 + q*4 + j;
            s_xT[c*64 + r] = ((vals[j]-mean)*rstd*s_c[c] + s_c[64+c]) * m;
        }
    }
    __syncthreads();

    // GEMM: 512 tiles (4x8), 2/thread
    for (int t = tid; t < 512; t += 256) {
        int rg = t & 15, cg = t >> 4;
        int r0 = rg*4, c0 = cg*8;
        uint64_t acc[4][4];
        #pragma unroll
        for (int j = 0; j < 4; j++) { uint64_t bb = pack2(s_c[128+c0+2*j], s_c[128+c0+2*j+1]);
            #pragma unroll
            for (int i = 0; i < 4; i++) acc[i][j] = bb; }
        gemm_48p<64,64,256>(s_xT, s_w, r0, c0, acc);
        #pragma unroll
        for (int i = 0; i < 4; i++) {
            float o[8];
            unpack2(acc[i][0], o[0], o[1]);
            unpack2(acc[i][1], o[2], o[3]);
            unpack2(acc[i][2], o[4], o[5]);
            unpack2(acc[i][3], o[6], o[7]);
            size_t ob = (size_t)(t0+r0+i)*CC + c00 + c0;
            #pragma unroll
            for (int j = 0; j < 8; j++)
                if (c00 + c0 + j < CC) out[ob + j] = o[j];
        }
    }
}

extern "C" void kernel_launch(void* const* d_in, const int* in_sizes, int n_in,
                              void* d_out, int out_size) {
    const float* ex    = (const float*)d_in[0];
    const int*   labels= (const int*)  d_in[1];
    const float* mask  = (const float*)d_in[2];
    const float* we    = (const float*)d_in[3];
    const float* be    = (const float*)d_in[4];
    const float* lemb  = (const float*)d_in[5];
    const float* w_in  = (const float*)d_in[6];
    const float* b_in  = (const float*)d_in[7];
    const float* ln1_s = (const float*)d_in[8];
    const float* ln1_b = (const float*)d_in[9];
    const float* wq    = (const float*)d_in[10];
    const float* bq    = (const float*)d_in[11];
    const float* wk    = (const float*)d_in[12];
    const float* bk    = (const float*)d_in[13];
    const float* wv    = (const float*)d_in[14];
    const float* bv    = (const float*)d_in[15];
    const float* wo    = (const float*)d_in[16];
    const float* bo    = (const float*)d_in[17];
    const float* ln2_s = (const float*)d_in[18];
    const float* ln2_b = (const float*)d_in[19];
    const float* w1    = (const float*)d_in[20];
    const float* b1    = (const float*)d_in[21];
    const float* w2    = (const float*)d_in[22];
    const float* b2    = (const float*)d_in[23];
    const float* lnf_s = (const float*)d_in[24];
    const float* lnf_b = (const float*)d_in[25];
    const float* w_out = (const float*)d_in[26];
    const float* b_out = (const float*)d_in[27];
    float* out = (float*)d_out;

    const int smem_embed = (2*128*68 + 128*128 + 192) * 4;
    const int smem_qkv   = (8192 + 8704 + 8192 + 320) * 4;
    const int smem_att   = (64*128 + 64*64 + 512 + 64 + 64) * 4;
    const int smem_ffn   = (8192 + 32768 + 8192 + 448) * 4;
    const int smem_out   = (64*64 + 64*256 + 384) * 4;

    cudaFuncSetAttribute(k_embed, cudaFuncAttributeMaxDynamicSharedMemorySize, smem_embed);
    cudaFuncSetAttribute(k_qkv,   cudaFuncAttributeMaxDynamicSharedMemorySize, smem_qkv);
    cudaFuncSetAttribute(k_att,   cudaFuncAttributeMaxDynamicSharedMemorySize, smem_att);
    cudaFuncSetAttribute(k_ffn,   cudaFuncAttributeMaxDynamicSharedMemorySize, smem_ffn);
    cudaFuncSetAttribute(k_out,   cudaFuncAttributeMaxDynamicSharedMemorySize, smem_out);

    k_embed<<<NTOK/64, 256, smem_embed>>>(ex, labels, we, be, lemb, w_in, b_in);
    for (int i = 0; i < NL; i++) {
        k_qkv<<<NTOK/128, 256, smem_qkv>>>(mask, ln1_s + i*DM, ln1_b + i*DM,
                                wq + i*DM*DM, bq + i*DM,
                                wk + i*DM*DM, bk + i*DM,
                                wv + i*DM*DM, bv + i*DM);
        k_kvcomb<<<(NB*NH*72 + 255)/256, 256>>>();
        k_att<<<NTOK/128, 256, smem_att>>>(wo + i*DM*DM, bo + i*DM);
        k_ffn<<<NTOK/128, 512, smem_ffn>>>(ln2_s + i*DM, ln2_b + i*DM,
                                 w1 + i*DM*FFD, b1 + i*FFD,
                                 w2 + i*FFD*DM, b2 + i*DM);
    }
    dim3 og(NTOK/64, (CC + 255)/256);
    k_out<<<og, 256, smem_out>>>(mask, lnf_s, lnf_b, w_out, b_out, out);
}

// round 11
// speedup vs baseline: 1.4062x; 1.4062x over previous
#include <cuda_runtime.h>
#include <cuda_bf16.h>
#include <cstdint>

// Problem constants
#define NB 16
#define SS 4096
#define NTOK (NB*SS)        // 65536
#define EE 128
#define DM 64
#define NH 8
#define DH 8
#define FFD 256
#define CC 1623
#define NL 8
#define SPLIT 8

// Scratch (device globals — allocation-free per harness rules)
__device__ float g_hh[NTOK*DM];
__device__ float g_pq[NTOK*DM];
__device__ float g_pk[NTOK*DM];
__device__ float g_v [NTOK*DM];
__device__ float g_kvp[NB*NH*SPLIT*72];

__device__ __forceinline__ float phi_f(float x) {
    return x > 0.f ? x + 1.f : __expf(x);   // elu(x)+1
}

__device__ __forceinline__ float gelu_f(float x) {
    float x3 = x * x * x;
    return 0.5f * x * (1.f + tanhf(0.7978845608028654f * (x + 0.044715f * x3)));
}

// ===================== packed f32x2 helpers (sm_100+ family-wide) =====================
__device__ __forceinline__ uint64_t pack2(float x, float y) {
    uint64_t r; asm("mov.b64 %0, {%1, %2};" : "=l"(r) : "f"(x), "f"(y)); return r;
}
__device__ __forceinline__ void unpack2(uint64_t v, float& x, float& y) {
    asm("mov.b64 {%0, %1}, %2;" : "=f"(x), "=f"(y) : "l"(v));
}
__device__ __forceinline__ void ffma2(uint64_t& d, uint64_t a, uint64_t b) {
    asm("fma.rn.f32x2 %0, %1, %2, %3;" : "=l"(d) : "l"(a), "l"(b), "l"(d));
}

// ---- packed register-tiled GEMM fragments: A transposed in smem [k][tok] (pitch PA),
// ---- W in smem [k][col] (pitch PW). acc[i][j] holds output cols (c0+2j, c0+2j+1).
template<int K, int PA, int PW>
__device__ __forceinline__ void gemm_48p(const float* __restrict__ AT,
                                         const float* __restrict__ Ws,
                                         int r0, int c0, uint64_t (&acc)[4][4]) {
    #pragma unroll 8
    for (int k = 0; k < K; k++) {
        float4 a = *(const float4*)(AT + k*PA + r0);
        ulonglong2 w01 = *(const ulonglong2*)(Ws + k*PW + c0);
        ulonglong2 w23 = *(const ulonglong2*)(Ws + k*PW + c0 + 4);
        uint64_t av[4] = {pack2(a.x,a.x), pack2(a.y,a.y), pack2(a.z,a.z), pack2(a.w,a.w)};
        uint64_t wv[4] = {w01.x, w01.y, w23.x, w23.y};
        #pragma unroll
        for (int i = 0; i < 4; i++)
            #pragma unroll
            for (int j = 0; j < 4; j++)
                ffma2(acc[i][j], av[i], wv[j]);
    }
}

template<int K, int PA, int PW>
__device__ __forceinline__ void gemm_44p(const float* __restrict__ AT,
                                         const float* __restrict__ Ws,
                                         int r0, int c0, uint64_t (&acc)[4][2]) {
    #pragma unroll 8
    for (int k = 0; k < K; k++) {
        float4 a = *(const float4*)(AT + k*PA + r0);
        ulonglong2 w01 = *(const ulonglong2*)(Ws + k*PW + c0);
        uint64_t av[4] = {pack2(a.x,a.x), pack2(a.y,a.y), pack2(a.z,a.z), pack2(a.w,a.w)};
        #pragma unroll
        for (int i = 0; i < 4; i++) {
            ffma2(acc[i][0], av[i], w01.x);
            ffma2(acc[i][1], av[i], w01.y);
        }
    }
}

// ================= Kernel 0: embedding =================
// hh = (ex@we + be + lemb[labels]) @ w_in + b_in ; 64 tokens/block
__global__ __launch_bounds__(256) void k_embed(
    const float* __restrict__ ex, const int* __restrict__ labels,
    const float* __restrict__ we, const float* __restrict__ be,
    const float* __restrict__ lemb, const float* __restrict__ w_in,
    const float* __restrict__ b_in)
{
    extern __shared__ float sm[];
    float* s_eT = sm;                // [128][68]  ex^T
    float* s_tT = sm + 128*68;       // [128][68]  tmp^T
    float* s_w  = sm + 2*128*68;     // max 128*128
    float* s_c  = s_w + 128*128;     // be(128) + b_in(64)
    const int tid = threadIdx.x;
    const int t0 = blockIdx.x * 64;

    for (int i = tid; i < 192; i += 256)
        s_c[i] = (i < 128) ? be[i] : b_in[i-128];
    for (int i = tid; i < 64*EE; i += 256) {
        int r = i >> 7, c = i & 127;
        s_eT[c*68 + r] = ex[(size_t)(t0+r)*EE + c];
    }
    for (int i = tid; i < EE*EE; i += 256) s_w[i] = we[i];
    __syncthreads();

    // stage A: tmp^T = (ex@we + be + lemb)^T
    {
        int rg = tid & 15, cg = tid >> 4;
        int r0 = rg*4, c0 = cg*8;
        uint64_t acc[4][4];
        #pragma unroll
        for (int j = 0; j < 4; j++) { uint64_t b = pack2(s_c[c0+2*j], s_c[c0+2*j+1]);
            #pragma unroll
            for (int i = 0; i < 4; i++) acc[i][j] = b; }
        gemm_48p<EE,68,EE>(s_eT, s_w, r0, c0, acc);
        #pragma unroll
        for (int i = 0; i < 4; i++) {
            int lab = labels[t0 + r0 + i];
            const float* le = lemb + (size_t)lab*EE + c0;
            #pragma unroll
            for (int j = 0; j < 4; j++) {
                float o0, o1; unpack2(acc[i][j], o0, o1);
                s_tT[(c0+2*j  )*68 + r0+i] = o0 + le[2*j];
                s_tT[(c0+2*j+1)*68 + r0+i] = o1 + le[2*j+1];
            }
        }
    }
    __syncthreads();
    for (int i = tid; i < EE*DM; i += 256) s_w[i] = w_in[i];
    __syncthreads();

    // stage B: hh = tmp@w_in + b_in
    {
        int rg = tid & 15, cg = tid >> 4;
        int r0 = rg*4, c0 = cg*4;
        uint64_t acc[4][2];
        #pragma unroll
        for (int j = 0; j < 2; j++) { uint64_t b = pack2(s_c[128+c0+2*j], s_c[128+c0+2*j+1]);
            #pragma unroll
            for (int i = 0; i < 4; i++) acc[i][j] = b; }
        gemm_44p<EE,68,DM>(s_tT, s_w, r0, c0, acc);
        #pragma unroll
        for (int i = 0; i < 4; i++) {
            float o0,o1,o2,o3;
            unpack2(acc[i][0], o0, o1);
            unpack2(acc[i][1], o2, o3);
            *(float4*)(g_hh + (size_t)(t0+r0+i)*DM + c0) = make_float4(o0,o1,o2,o3);
        }
    }
}

// ================= Kernel 1: mask + LN1 + QKV (+phi) =================
// 128 tokens/block
__global__ __launch_bounds__(256) void k_qkv(
    const float* __restrict__ mask,
    const float* __restrict__ ls, const float* __restrict__ lb,
    const float* __restrict__ wq, const float* __restrict__ bq,
    const float* __restrict__ wk, const float* __restrict__ bk,
    const float* __restrict__ wv, const float* __restrict__ bv)
{
    extern __shared__ float sm[];
    float* s_xT = sm;              // [64][128]
    float* s_w  = sm + 64*128;     // [64][192] q|k|v
    float* s_c  = s_w + 64*192;    // ls(64) lb(64) bq|bk|bv(192)
    const int tid = threadIdx.x;
    const int t0 = blockIdx.x * 128;

    for (int i = tid; i < 320; i += 256) {
        float v;
        if      (i < 64)  v = ls[i];
        else if (i < 128) v = lb[i-64];
        else if (i < 192) v = bq[i-128];
        else if (i < 256) v = bk[i-192];
        else              v = bv[i-256];
        s_c[i] = v;
    }
    for (int i = tid; i < 64*192; i += 256) {
        int k = i / 192, c = i % 192;
        const float* W = (c < 64) ? wq : (c < 128) ? wk : wv;
        s_w[i] = W[k*DM + (c & 63)];
    }

    // LN in registers (2 threads / row, 32 cols each)
    const int r = tid >> 1, g = tid & 1;
    const int n = t0 + r;
    float m = mask[n];
    float4 vv[8];
    {
        const float4* src = (const float4*)(g_hh + (size_t)n*DM + g*32);
        #pragma unroll
        for (int q = 0; q < 8; q++) {
            float4 v = src[q];
            v.x*=m; v.y*=m; v.z*=m; v.w*=m;
            vv[q] = v;
        }
        float4* dst = (float4*)(g_hh + (size_t)n*DM + g*32);
        #pragma unroll
        for (int q = 0; q < 8; q++) dst[q] = vv[q];   // hh *= mask (residual base)
    }
    float sum = 0.f, sq = 0.f;
    #pragma unroll
    for (int q = 0; q < 8; q++) {
        sum += vv[q].x+vv[q].y+vv[q].z+vv[q].w;
        sq  += vv[q].x*vv[q].x+vv[q].y*vv[q].y+vv[q].z*vv[q].z+vv[q].w*vv[q].w;
    }
    sum += __shfl_xor_sync(0xffffffffu, sum, 1);
    sq  += __shfl_xor_sync(0xffffffffu, sq , 1);
    float mean = sum * (1.f/64.f);
    float rstd = rsqrtf(sq * (1.f/64.f) - mean*mean + 1e-5f);
    __syncthreads();

    #pragma unroll
    for (int q = 0; q < 8; q++) {
        float vals[4] = {vv[q].x,vv[q].y,vv[q].z,vv[q].w};
        #pragma unroll
        for (int j = 0; j < 4; j++) {
            int c = g*32 + q*4 + j;
            s_xT[c*128 + r] = (vals[j]-mean)*rstd*s_c[c] + s_c[64+c];
        }
    }
    __syncthreads();

    // GEMM: [128 tok] x [64 k] x [192 cols]; 768 tiles of 4x8, 3/thread
    for (int t = tid; t < 768; t += 256) {
        int rg = t & 31, cg = t >> 5;
        int r0 = rg*4, c0 = cg*8;
        uint64_t acc[4][4];
        #pragma unroll
        for (int j = 0; j < 4; j++) { uint64_t b = pack2(s_c[128+c0+2*j], s_c[128+c0+2*j+1]);
            #pragma unroll
            for (int i = 0; i < 4; i++) acc[i][j] = b; }
        gemm_48p<64,128,192>(s_xT, s_w, r0, c0, acc);
        int which = c0 >> 6, cc = c0 & 63;
        #pragma unroll
        for (int i = 0; i < 4; i++) {
            int nn = t0 + r0 + i;
            float o[8];
            unpack2(acc[i][0], o[0], o[1]);
            unpack2(acc[i][1], o[2], o[3]);
            unpack2(acc[i][2], o[4], o[5]);
            unpack2(acc[i][3], o[6], o[7]);
            if (which == 0) {
                float4 o0 = make_float4(phi_f(o[0]),phi_f(o[1]),phi_f(o[2]),phi_f(o[3]));
                float4 o1 = make_float4(phi_f(o[4]),phi_f(o[5]),phi_f(o[6]),phi_f(o[7]));
                *(float4*)(g_pq + (size_t)nn*DM + cc)     = o0;
                *(float4*)(g_pq + (size_t)nn*DM + cc + 4) = o1;
            } else if (which == 1) {
                float mm = mask[nn];
                float4 o0 = make_float4(phi_f(o[0])*mm,phi_f(o[1])*mm,phi_f(o[2])*mm,phi_f(o[3])*mm);
                float4 o1 = make_float4(phi_f(o[4])*mm,phi_f(o[5])*mm,phi_f(o[6])*mm,phi_f(o[7])*mm);
                *(float4*)(g_pk + (size_t)nn*DM + cc)     = o0;
                *(float4*)(g_pk + (size_t)nn*DM + cc + 4) = o1;
            } else {
                *(float4*)(g_v + (size_t)nn*DM + cc)     = make_float4(o[0],o[1],o[2],o[3]);
                *(float4*)(g_v + (size_t)nn*DM + cc + 4) = make_float4(o[4],o[5],o[6],o[7]);
            }
        }
    }
}

// ================= Kernel 2: kv-state reduction (deterministic) =================
__global__ __launch_bounds__(256) void k_kvred() {
    __shared__ float s_red[8][72];
    int bh = blockIdx.x / SPLIT, chunk = blockIdx.x % SPLIT;
    int b = bh >> 3, h = bh & 7;
    int tid = threadIdx.x, wid = tid >> 5, lane = tid & 31;
    float kv[8][8] = {}; float ks[8] = {};
    int s0 = chunk * (SS / SPLIT);
    for (int s = s0 + tid; s < s0 + SS/SPLIT; s += 256) {
        int base = (b*SS + s)*DM + h*8;
        float4 p0 = *(const float4*)(g_pk + base), p1 = *(const float4*)(g_pk + base + 4);
        float4 v0 = *(const float4*)(g_v  + base), v1 = *(const float4*)(g_v  + base + 4);
        float pk[8] = {p0.x,p0.y,p0.z,p0.w,p1.x,p1.y,p1.z,p1.w};
        float vvv[8] = {v0.x,v0.y,v0.z,v0.w,v1.x,v1.y,v1.z,v1.w};
        #pragma unroll
        for (int d = 0; d < 8; d++) {
            ks[d] += pk[d];
            #pragma unroll
            for (int e = 0; e < 8; e++) kv[d][e] += pk[d]*vvv[e];
        }
    }
    #pragma unroll
    for (int o = 16; o > 0; o >>= 1) {
        #pragma unroll
        for (int d = 0; d < 8; d++) {
            ks[d] += __shfl_down_sync(0xffffffffu, ks[d], o);
            #pragma unroll
            for (int e = 0; e < 8; e++)
                kv[d][e] += __shfl_down_sync(0xffffffffu, kv[d][e], o);
        }
    }
    if (lane == 0) {
        #pragma unroll
        for (int d = 0; d < 8; d++) {
            #pragma unroll
            for (int e = 0; e < 8; e++) s_red[wid][d*8+e] = kv[d][e];
            s_red[wid][64+d] = ks[d];
        }
    }
    __syncthreads();
    if (tid < 72) {
        float acc = 0.f;
        #pragma unroll
        for (int w = 0; w < 8; w++) acc += s_red[w][tid];
        g_kvp[(size_t)blockIdx.x*72 + tid] = acc;
    }
}

// ================= Kernel 3: kv-combine + attention readout + @wo + residual =================
// 128 tokens/block
__global__ __launch_bounds__(256) void k_att(
    const float* __restrict__ wo, const float* __restrict__ bo)
{
    extern __shared__ float sm[];
    float* s_attT = sm;               // [64][128]
    float* s_w    = sm + 64*128;      // wo [64][64]
    float* s_kv   = s_w + 64*64;      // 512
    float* s_ks   = s_kv + 512;       // 64
    float* s_bo   = s_ks + 64;        // 64
    const int tid = threadIdx.x;
    const int t0 = blockIdx.x * 128;
    const int b = t0 >> 12;           // t0 / SS

    for (int i = tid; i < 64*64; i += 256) s_w[i] = wo[i];
    // fused kv-combine
    for (int i = tid; i < NH*72; i += 256) {
        int h = i / 72, idx = i % 72;
        float acc = 0.f;
        #pragma unroll
        for (int c = 0; c < SPLIT; c++)
            acc += g_kvp[(size_t)((b*NH + h)*SPLIT + c)*72 + idx];
        if (idx < 64) s_kv[h*64 + idx] = acc;
        else          s_ks[h*8 + idx - 64] = acc;
    }
    if (tid < 64) s_bo[tid] = bo[tid];

    const int r = tid >> 1, g = tid & 1;
    const int n = t0 + r;
    float p[32];
    {
        const float4* src = (const float4*)(g_pq + (size_t)n*DM + g*32);
        #pragma unroll
        for (int q = 0; q < 8; q++) {
            float4 v = src[q];
            p[q*4+0]=v.x; p[q*4+1]=v.y; p[q*4+2]=v.z; p[q*4+3]=v.w;
        }
    }
    __syncthreads();

    #pragma unroll
    for (int u = 0; u < 4; u++) {
        int h = g*4 + u;
        float den = 0.f;
        #pragma unroll
        for (int d = 0; d < 8; d++) den += p[u*8+d] * s_ks[h*8+d];
        float inv = 1.f / (den + 1e-6f);
        const float* kvb = s_kv + h*64;
        #pragma unroll
        for (int e = 0; e < 8; e++) {
            float num = 0.f;
            #pragma unroll
            for (int d = 0; d < 8; d++) num += p[u*8+d] * kvb[d*8+e];
            s_attT[(g*32 + u*8 + e)*128 + r] = num * inv;
        }
    }
    __syncthreads();

    // GEMM att@wo + bo, += hh ; 256 tiles (4x8), 1/thread
    {
        int rg = tid & 31, cg = tid >> 5;
        int r0 = rg*4, c0 = cg*8;
        uint64_t acc[4][4];
        #pragma unroll
        for (int j = 0; j < 4; j++) { uint64_t bb = pack2(s_bo[c0+2*j], s_bo[c0+2*j+1]);
            #pragma unroll
            for (int i = 0; i < 4; i++) acc[i][j] = bb; }
        gemm_48p<64,128,64>(s_attT, s_w, r0, c0, acc);
        #pragma unroll
        for (int i = 0; i < 4; i++) {
            float o[8];
            unpack2(acc[i][0], o[0], o[1]);
            unpack2(acc[i][1], o[2], o[3]);
            unpack2(acc[i][2], o[4], o[5]);
            unpack2(acc[i][3], o[6], o[7]);
            float4* ph = (float4*)(g_hh + (size_t)(t0+r0+i)*DM + c0);
            float4 h0 = ph[0], h1 = ph[1];
            h0.x += o[0]; h0.y += o[1]; h0.z += o[2]; h0.w += o[3];
            h1.x += o[4]; h1.y += o[5]; h1.z += o[6]; h1.w += o[7];
            ph[0] = h0; ph[1] = h1;
        }
    }
}

// ================= Kernel 4: fused LN2 + FFN(up,gelu,down) + residual =================
// 64 tokens/block, t1 tile lives in smem (no global round-trip)
__global__ __launch_bounds__(256) void k_ffn(
    const float* __restrict__ ls, const float* __restrict__ lb,
    const float* __restrict__ w1, const float* __restrict__ b1,
    const float* __restrict__ w2, const float* __restrict__ b2)
{
    extern __shared__ float sm[];
    float* s_yT  = sm;                 // [64][64]
    float* s_t1T = sm + 64*64;         // [256][64]
    float* s_w   = s_t1T + 256*64;     // 64*128 staging buffer
    float* s_c   = s_w + 64*128;       // ls 64 | lb 64 | b1 256 | b2 64 = 448
    const int tid = threadIdx.x;
    const int t0 = blockIdx.x * 64;

    for (int i = tid; i < 448; i += 256) {
        float v;
        if      (i < 64)  v = ls[i];
        else if (i < 128) v = lb[i-64];
        else if (i < 384) v = b1[i-128];
        else              v = b2[i-384];
        s_c[i] = v;
    }

    // LN2 in registers (4 threads / row, 16 cols each)
    const int r = tid >> 2, g = tid & 3;
    const int n = t0 + r;
    float4 vv[4];
    {
        const float4* src = (const float4*)(g_hh + (size_t)n*DM + g*16);
        #pragma unroll
        for (int q = 0; q < 4; q++) vv[q] = src[q];
    }
    float sum = 0.f, sq = 0.f;
    #pragma unroll
    for (int q = 0; q < 4; q++) {
        sum += vv[q].x+vv[q].y+vv[q].z+vv[q].w;
        sq  += vv[q].x*vv[q].x+vv[q].y*vv[q].y+vv[q].z*vv[q].z+vv[q].w*vv[q].w;
    }
    sum += __shfl_xor_sync(0xffffffffu, sum, 1);
    sq  += __shfl_xor_sync(0xffffffffu, sq , 1);
    sum += __shfl_xor_sync(0xffffffffu, sum, 2);
    sq  += __shfl_xor_sync(0xffffffffu, sq , 2);
    float mean = sum * (1.f/64.f);
    float rstd = rsqrtf(sq * (1.f/64.f) - mean*mean + 1e-5f);
    __syncthreads();   // s_c staged

    #pragma unroll
    for (int q = 0; q < 4; q++) {
        float vals[4] = {vv[q].x,vv[q].y,vv[q].z,vv[q].w};
        #pragma unroll
        for (int j = 0; j < 4; j++) {
            int c = g*16 + q*4 + j;
            s_yT[c*64 + r] = (vals[j]-mean)*rstd*s_c[c] + s_c[64+c];
        }
    }

    // FFN up: two 128-col halves, weights staged per half
    for (int h01 = 0; h01 < 2; h01++) {
        __syncthreads();   // yT ready / prior s_w reads done
        for (int i = tid; i < 64*128; i += 256) {
            int k = i >> 7, c = i & 127;
            s_w[i] = w1[k*FFD + h01*128 + c];
        }
        __syncthreads();
        int rg = tid & 15, cg = tid >> 4;
        int r0 = rg*4, c0 = cg*8;
        uint64_t acc[4][4];
        #pragma unroll
        for (int j = 0; j < 4; j++) { uint64_t bb = pack2(s_c[128 + h01*128 + c0+2*j], s_c[128 + h01*128 + c0+2*j+1]);
            #pragma unroll
            for (int i = 0; i < 4; i++) acc[i][j] = bb; }
        gemm_48p<64,64,128>(s_yT, s_w, r0, c0, acc);
        #pragma unroll
        for (int i = 0; i < 4; i++) {
            #pragma unroll
            for (int j = 0; j < 4; j++) {
                float o0, o1; unpack2(acc[i][j], o0, o1);
                s_t1T[(h01*128 + c0+2*j  )*64 + r0+i] = gelu_f(o0);
                s_t1T[(h01*128 + c0+2*j+1)*64 + r0+i] = gelu_f(o1);
            }
        }
    }

    // FFN down: K=256 in two halves, accumulator persists
    const int rg2 = tid & 15, cg2 = tid >> 4;
    const int r0b = rg2*4, c0b = cg2*4;
    uint64_t acc2[4][2];
    #pragma unroll
    for (int j = 0; j < 2; j++) { uint64_t bb = pack2(s_c[384 + c0b+2*j], s_c[384 + c0b+2*j+1]);
        #pragma unroll
        for (int i = 0; i < 4; i++) acc2[i][j] = bb; }
    for (int kh = 0; kh < 2; kh++) {
        __syncthreads();
        for (int i = tid; i < 128*64; i += 256) {
            int k = i >> 6, c = i & 63;
            s_w[i] = w2[(size_t)(kh*128 + k)*DM + c];
        }
        __syncthreads();
        gemm_44p<128,64,64>(s_t1T + kh*128*64, s_w, r0b, c0b, acc2);
    }
    #pragma unroll
    for (int i = 0; i < 4; i++) {
        float o0,o1,o2,o3;
        unpack2(acc2[i][0], o0, o1);
        unpack2(acc2[i][1], o2, o3);
        float4* ph = (float4*)(g_hh + (size_t)(t0+r0b+i)*DM + c0b);
        float4 h0 = *ph;
        h0.x += o0; h0.y += o1; h0.z += o2; h0.w += o3;
        *ph = h0;
    }
}

// ================= Kernel 5: final LN + mask + output GEMM =================
// 128 tokens/block x 256-col chunks (halves w_out staging traffic vs 64-tok)
__global__ __launch_bounds__(256) void k_out(
    const float* __restrict__ mask,
    const float* __restrict__ ls, const float* __restrict__ lb,
    const float* __restrict__ w_out, const float* __restrict__ b_out,
    float* __restrict__ out)
{
    extern __shared__ float sm[];
    float* s_xT = sm;               // [64][128]
    float* s_w  = sm + 64*128;      // [64][256] chunk
    float* s_c  = s_w + 64*256;     // ls 64 | lb 64 | bias 256
    const int tid = threadIdx.x;
    const int t0 = blockIdx.x * 128;
    const int c00 = blockIdx.y * 256;

    for (int i = tid; i < 384; i += 256) {
        float v;
        if      (i < 64)  v = ls[i];
        else if (i < 128) v = lb[i-64];
        else { int c = c00 + i - 128; v = (c < CC) ? b_out[c] : 0.f; }
        s_c[i] = v;
    }
    for (int i = tid; i < 64*256; i += 256) {
        int k = i >> 8, j = i & 255;
        int c = c00 + j;
        s_w[i] = (c < CC) ? w_out[(size_t)k*CC + c] : 0.f;
    }

    // final LN (+mask) in registers (2 threads / row, 32 cols each)
    const int r = tid >> 1, g = tid & 1;
    const int n = t0 + r;
    float4 vv[8];
    {
        const float4* src = (const float4*)(g_hh + (size_t)n*DM + g*32);
        #pragma unroll
        for (int q = 0; q < 8; q++) vv[q] = src[q];
    }
    float sum = 0.f, sq = 0.f;
    #pragma unroll
    for (int q = 0; q < 8; q++) {
        sum += vv[q].x+vv[q].y+vv[q].z+vv[q].w;
        sq  += vv[q].x*vv[q].x+vv[q].y*vv[q].y+vv[q].z*vv[q].z+vv[q].w*vv[q].w;
    }
    sum += __shfl_xor_sync(0xffffffffu, sum, 1);
    sq  += __shfl_xor_sync(0xffffffffu, sq , 1);
    float mean = sum * (1.f/64.f);
    float rstd = rsqrtf(sq * (1.f/64.f) - mean*mean + 1e-5f);
    float m = mask[n];
    __syncthreads();

    #pragma unroll
    for (int q = 0; q < 8; q++) {
        float vals[4] = {vv[q].x,vv[q].y,vv[q].z,vv[q].w};
        #pragma unroll
        for (int j = 0; j < 4; j++) {
            int c = g*32 + q*4 + j;
            s_xT[c*128 + r] = ((vals[j]-mean)*rstd*s_c[c] + s_c[64+c]) * m;
        }
    }
    __syncthreads();

    // GEMM: 128 tok x 256 cols = 1024 tiles (4x8), 4/thread
    for (int t = tid; t < 1024; t += 256) {
        int rg = t & 31, cg = t >> 5;
        int r0 = rg*4, c0 = cg*8;
        uint64_t acc[4][4];
        #pragma unroll
        for (int j = 0; j < 4; j++) { uint64_t bb = pack2(s_c[128+c0+2*j], s_c[128+c0+2*j+1]);
            #pragma unroll
            for (int i = 0; i < 4; i++) acc[i][j] = bb; }
        gemm_48p<64,128,256>(s_xT, s_w, r0, c0, acc);
        #pragma unroll
        for (int i = 0; i < 4; i++) {
            float o[8];
            unpack2(acc[i][0], o[0], o[1]);
            unpack2(acc[i][1], o[2], o[3]);
            unpack2(acc[i][2], o[4], o[5]);
            unpack2(acc[i][3], o[6], o[7]);
            size_t ob = (size_t)(t0+r0+i)*CC + c00 + c0;
            #pragma unroll
            for (int j = 0; j < 8; j++)
                if (c00 + c0 + j < CC) out[ob + j] = o[j];
        }
    }
}

extern "C" void kernel_launch(void* const* d_in, const int* in_sizes, int n_in,
                              void* d_out, int out_size) {
    const float* ex    = (const float*)d_in[0];
    const int*   labels= (const int*)  d_in[1];
    const float* mask  = (const float*)d_in[2];
    const float* we    = (const float*)d_in[3];
    const float* be    = (const float*)d_in[4];
    const float* lemb  = (const float*)d_in[5];
    const float* w_in  = (const float*)d_in[6];
    const float* b_in  = (const float*)d_in[7];
    const float* ln1_s = (const float*)d_in[8];
    const float* ln1_b = (const float*)d_in[9];
    const float* wq    = (const float*)d_in[10];
    const float* bq    = (const float*)d_in[11];
    const float* wk    = (const float*)d_in[12];
    const float* bk    = (const float*)d_in[13];
    const float* wv    = (const float*)d_in[14];
    const float* bv    = (const float*)d_in[15];
    const float* wo    = (const float*)d_in[16];
    const float* bo    = (const float*)d_in[17];
    const float* ln2_s = (const float*)d_in[18];
    const float* ln2_b = (const float*)d_in[19];
    const float* w1    = (const float*)d_in[20];
    const float* b1    = (const float*)d_in[21];
    const float* w2    = (const float*)d_in[22];
    const float* b2    = (const float*)d_in[23];
    const float* lnf_s = (const float*)d_in[24];
    const float* lnf_b = (const float*)d_in[25];
    const float* w_out = (const float*)d_in[26];
    const float* b_out = (const float*)d_in[27];
    float* out = (float*)d_out;

    const int smem_embed = (2*128*68 + 128*128 + 192) * 4;
    const int smem_qkv   = (64*128 + 64*192 + 320) * 4;
    const int smem_att   = (64*128 + 64*64 + 512 + 64 + 64) * 4;
    const int smem_ffn   = (64*64 + 256*64 + 64*128 + 448) * 4;
    const int smem_out   = (64*128 + 64*256 + 384) * 4;

    cudaFuncSetAttribute(k_embed, cudaFuncAttributeMaxDynamicSharedMemorySize, smem_embed);
    cudaFuncSetAttribute(k_qkv,   cudaFuncAttributeMaxDynamicSharedMemorySize, smem_qkv);
    cudaFuncSetAttribute(k_att,   cudaFuncAttributeMaxDynamicSharedMemorySize, smem_att);
    cudaFuncSetAttribute(k_ffn,   cudaFuncAttributeMaxDynamicSharedMemorySize, smem_ffn);
    cudaFuncSetAttribute(k_out,   cudaFuncAttributeMaxDynamicSharedMemorySize, smem_out);

    k_embed<<<NTOK/64, 256, smem_embed>>>(ex, labels, we, be, lemb, w_in, b_in);
    for (int i = 0; i < NL; i++) {
        k_qkv<<<NTOK/128, 256, smem_qkv>>>(mask, ln1_s + i*DM, ln1_b + i*DM,
                                wq + i*DM*DM, bq + i*DM,
                                wk + i*DM*DM, bk + i*DM,
                                wv + i*DM*DM, bv + i*DM);
        k_kvred<<<NB*NH*SPLIT, 256>>>();
        k_att<<<NTOK/128, 256, smem_att>>>(wo + i*DM*DM, bo + i*DM);
        k_ffn<<<NTOK/64, 256, smem_ffn>>>(ln2_s + i*DM, ln2_b + i*DM,
                                 w1 + i*DM*FFD, b1 + i*FFD,
                                 w2 + i*FFD*DM, b2 + i*DM);
    }
    dim3 og(NTOK/128, (CC + 255)/256);
    k_out<<<og, 256, smem_out>>>(mask, lnf_s, lnf_b, w_out, b_out, out);
}

// round 12
// speedup vs baseline: 1.6022x; 1.1394x over previous
#include <cuda_runtime.h>
#include <cuda_bf16.h>
#include <cstdint>

// Problem constants
#define NB 16
#define SS 4096
#define NTOK (NB*SS)        // 65536
#define EE 128
#define DM 64
#define NH 8
#define DH 8
#define FFD 256
#define CC 1623
#define NL 8
#define SPLIT 8

// Scratch (device globals — allocation-free per harness rules)
__device__ float g_hh[NTOK*DM];
__device__ float g_pq[NTOK*DM];
__device__ float g_pk[NTOK*DM];
__device__ float g_v [NTOK*DM];
__device__ float g_kvp[NB*NH*SPLIT*72];

__device__ __forceinline__ float phi_f(float x) {
    return x > 0.f ? x + 1.f : __expf(x);   // elu(x)+1
}

__device__ __forceinline__ float gelu_f(float x) {
    float x3 = x * x * x;
    return 0.5f * x * (1.f + tanhf(0.7978845608028654f * (x + 0.044715f * x3)));
}

// ===================== packed f32x2 helpers =====================
__device__ __forceinline__ uint64_t pack2(float x, float y) {
    uint64_t r; asm("mov.b64 %0, {%1, %2};" : "=l"(r) : "f"(x), "f"(y)); return r;
}
__device__ __forceinline__ void unpack2(uint64_t v, float& x, float& y) {
    asm("mov.b64 {%0, %1}, %2;" : "=f"(x), "=f"(y) : "l"(v));
}
__device__ __forceinline__ void ffma2(uint64_t& d, uint64_t a, uint64_t b) {
    asm("fma.rn.f32x2 %0, %1, %2, %3;" : "=l"(d) : "l"(a), "l"(b), "l"(d));
}

// ---- packed register-tiled GEMM fragments: A transposed in smem [k][tok] (pitch PA),
// ---- W in smem [k][col] (pitch PW). acc[i][j] holds output cols (c0+2j, c0+2j+1).
template<int K, int PA, int PW>
__device__ __forceinline__ void gemm_48p(const float* __restrict__ AT,
                                         const float* __restrict__ Ws,
                                         int r0, int c0, uint64_t (&acc)[4][4]) {
    #pragma unroll 8
    for (int k = 0; k < K; k++) {
        float4 a = *(const float4*)(AT + k*PA + r0);
        ulonglong2 w01 = *(const ulonglong2*)(Ws + k*PW + c0);
        ulonglong2 w23 = *(const ulonglong2*)(Ws + k*PW + c0 + 4);
        uint64_t av[4] = {pack2(a.x,a.x), pack2(a.y,a.y), pack2(a.z,a.z), pack2(a.w,a.w)};
        uint64_t wv[4] = {w01.x, w01.y, w23.x, w23.y};
        #pragma unroll
        for (int i = 0; i < 4; i++)
            #pragma unroll
            for (int j = 0; j < 4; j++)
                ffma2(acc[i][j], av[i], wv[j]);
    }
}

template<int K, int PA, int PW>
__device__ __forceinline__ void gemm_44p(const float* __restrict__ AT,
                                         const float* __restrict__ Ws,
                                         int r0, int c0, uint64_t (&acc)[4][2]) {
    #pragma unroll 8
    for (int k = 0; k < K; k++) {
        float4 a = *(const float4*)(AT + k*PA + r0);
        ulonglong2 w01 = *(const ulonglong2*)(Ws + k*PW + c0);
        uint64_t av[4] = {pack2(a.x,a.x), pack2(a.y,a.y), pack2(a.z,a.z), pack2(a.w,a.w)};
        #pragma unroll
        for (int i = 0; i < 4; i++) {
            ffma2(acc[i][0], av[i], w01.x);
            ffma2(acc[i][1], av[i], w01.y);
        }
    }
}

// ================= Kernel 0: embedding =================
// hh = (ex@we + be + lemb[labels]) @ w_in + b_in ; 64 tokens/block
// we staged in two 64-col halves -> smem ~101 KB -> 2 blocks/SM
__global__ __launch_bounds__(256, 2) void k_embed(
    const float* __restrict__ ex, const int* __restrict__ labels,
    const float* __restrict__ we, const float* __restrict__ be,
    const float* __restrict__ lemb, const float* __restrict__ w_in,
    const float* __restrict__ b_in)
{
    extern __shared__ float sm[];
    float* s_eT = sm;                // [128][68]  ex^T
    float* s_tT = sm + 128*68;       // [128][68]  tmp^T
    float* s_w  = sm + 2*128*68;     // [128][64] staging
    float* s_c  = s_w + 128*64;      // be(128) + b_in(64)
    const int tid = threadIdx.x;
    const int t0 = blockIdx.x * 64;
    const int rg = tid & 15, cg = tid >> 4;
    const int r0 = rg*4, c0 = cg*4;

    for (int i = tid; i < 192; i += 256)
        s_c[i] = (i < 128) ? be[i] : b_in[i-128];
    for (int i = tid; i < 64*EE; i += 256) {
        int r = i >> 7, c = i & 127;
        s_eT[c*68 + r] = ex[(size_t)(t0+r)*EE + c];
    }

    // stage A in two 64-col halves of we
    for (int h = 0; h < 2; h++) {
        __syncthreads();
        for (int i = tid; i < EE*64; i += 256) {
            int k = i >> 6, j = i & 63;
            s_w[i] = we[k*EE + h*64 + j];
        }
        __syncthreads();
        uint64_t acc[4][2];
        #pragma unroll
        for (int j = 0; j < 2; j++) { uint64_t b = pack2(s_c[h*64+c0+2*j], s_c[h*64+c0+2*j+1]);
            #pragma unroll
            for (int i = 0; i < 4; i++) acc[i][j] = b; }
        gemm_44p<EE,68,64>(s_eT, s_w, r0, c0, acc);
        #pragma unroll
        for (int i = 0; i < 4; i++) {
            int lab = labels[t0 + r0 + i];
            const float* le = lemb + (size_t)lab*EE + h*64 + c0;
            float o0,o1,o2,o3;
            unpack2(acc[i][0], o0, o1);
            unpack2(acc[i][1], o2, o3);
            s_tT[(h*64+c0+0)*68 + r0+i] = o0 + le[0];
            s_tT[(h*64+c0+1)*68 + r0+i] = o1 + le[1];
            s_tT[(h*64+c0+2)*68 + r0+i] = o2 + le[2];
            s_tT[(h*64+c0+3)*68 + r0+i] = o3 + le[3];
        }
    }
    __syncthreads();
    for (int i = tid; i < EE*DM; i += 256) s_w[i] = w_in[i];
    __syncthreads();

    // stage B: hh = tmp@w_in + b_in
    {
        uint64_t acc[4][2];
        #pragma unroll
        for (int j = 0; j < 2; j++) { uint64_t b = pack2(s_c[128+c0+2*j], s_c[128+c0+2*j+1]);
            #pragma unroll
            for (int i = 0; i < 4; i++) acc[i][j] = b; }
        gemm_44p<EE,68,64>(s_tT, s_w, r0, c0, acc);
        #pragma unroll
        for (int i = 0; i < 4; i++) {
            float o0,o1,o2,o3;
            unpack2(acc[i][0], o0, o1);
            unpack2(acc[i][1], o2, o3);
            *(float4*)(g_hh + (size_t)(t0+r0+i)*DM + c0) = make_float4(o0,o1,o2,o3);
        }
    }
}

// ================= Kernel 1: mask + LN1 + QKV (+phi) =================
// 128 tokens/block; weights staged in two passes (wq|wk then wv) -> smem 65 KB -> 3 blocks/SM
__global__ __launch_bounds__(256, 3) void k_qkv(
    const float* __restrict__ mask,
    const float* __restrict__ ls, const float* __restrict__ lb,
    const float* __restrict__ wq, const float* __restrict__ bq,
    const float* __restrict__ wk, const float* __restrict__ bk,
    const float* __restrict__ wv, const float* __restrict__ bv)
{
    extern __shared__ float sm[];
    float* s_xT = sm;              // [64][128]
    float* s_w  = sm + 64*128;     // [64][128] staging (q|k, then v)
    float* s_c  = s_w + 64*128;    // ls(64) lb(64) bq|bk|bv(192)
    const int tid = threadIdx.x;
    const int t0 = blockIdx.x * 128;

    for (int i = tid; i < 320; i += 256) {
        float v;
        if      (i < 64)  v = ls[i];
        else if (i < 128) v = lb[i-64];
        else if (i < 192) v = bq[i-128];
        else if (i < 256) v = bk[i-192];
        else              v = bv[i-256];
        s_c[i] = v;
    }
    // stage [wq|wk]
    for (int i = tid; i < 64*128; i += 256) {
        int k = i >> 7, c = i & 127;
        s_w[i] = (c < 64) ? wq[k*DM + c] : wk[k*DM + (c-64)];
    }

    // LN in registers (2 threads / row, 32 cols each)
    const int r = tid >> 1, g = tid & 1;
    const int n = t0 + r;
    float m = mask[n];
    float4 vv[8];
    {
        const float4* src = (const float4*)(g_hh + (size_t)n*DM + g*32);
        #pragma unroll
        for (int q = 0; q < 8; q++) {
            float4 v = src[q];
            v.x*=m; v.y*=m; v.z*=m; v.w*=m;
            vv[q] = v;
        }
        float4* dst = (float4*)(g_hh + (size_t)n*DM + g*32);
        #pragma unroll
        for (int q = 0; q < 8; q++) dst[q] = vv[q];   // hh *= mask (residual base)
    }
    float sum = 0.f, sq = 0.f;
    #pragma unroll
    for (int q = 0; q < 8; q++) {
        sum += vv[q].x+vv[q].y+vv[q].z+vv[q].w;
        sq  += vv[q].x*vv[q].x+vv[q].y*vv[q].y+vv[q].z*vv[q].z+vv[q].w*vv[q].w;
    }
    sum += __shfl_xor_sync(0xffffffffu, sum, 1);
    sq  += __shfl_xor_sync(0xffffffffu, sq , 1);
    float mean = sum * (1.f/64.f);
    float rstd = rsqrtf(sq * (1.f/64.f) - mean*mean + 1e-5f);
    __syncthreads();

    #pragma unroll
    for (int q = 0; q < 8; q++) {
        float vals[4] = {vv[q].x,vv[q].y,vv[q].z,vv[q].w};
        #pragma unroll
        for (int j = 0; j < 4; j++) {
            int c = g*32 + q*4 + j;
            s_xT[c*128 + r] = (vals[j]-mean)*rstd*s_c[c] + s_c[64+c];
        }
    }
    __syncthreads();

    // pass A: q|k (128 cols); 512 tiles of 4x8, 2/thread
    for (int t = tid; t < 512; t += 256) {
        int rg = t & 31, cg = t >> 5;
        int r0 = rg*4, c0 = cg*8;
        uint64_t acc[4][4];
        #pragma unroll
        for (int j = 0; j < 4; j++) { uint64_t b = pack2(s_c[128+c0+2*j], s_c[128+c0+2*j+1]);
            #pragma unroll
            for (int i = 0; i < 4; i++) acc[i][j] = b; }
        gemm_48p<64,128,128>(s_xT, s_w, r0, c0, acc);
        #pragma unroll
        for (int i = 0; i < 4; i++) {
            int nn = t0 + r0 + i;
            float o[8];
            unpack2(acc[i][0], o[0], o[1]);
            unpack2(acc[i][1], o[2], o[3]);
            unpack2(acc[i][2], o[4], o[5]);
            unpack2(acc[i][3], o[6], o[7]);
            if (c0 < 64) {
                float4 o0 = make_float4(phi_f(o[0]),phi_f(o[1]),phi_f(o[2]),phi_f(o[3]));
                float4 o1 = make_float4(phi_f(o[4]),phi_f(o[5]),phi_f(o[6]),phi_f(o[7]));
                *(float4*)(g_pq + (size_t)nn*DM + c0)     = o0;
                *(float4*)(g_pq + (size_t)nn*DM + c0 + 4) = o1;
            } else {
                int cc = c0 - 64;
                float mm = mask[nn];
                float4 o0 = make_float4(phi_f(o[0])*mm,phi_f(o[1])*mm,phi_f(o[2])*mm,phi_f(o[3])*mm);
                float4 o1 = make_float4(phi_f(o[4])*mm,phi_f(o[5])*mm,phi_f(o[6])*mm,phi_f(o[7])*mm);
                *(float4*)(g_pk + (size_t)nn*DM + cc)     = o0;
                *(float4*)(g_pk + (size_t)nn*DM + cc + 4) = o1;
            }
        }
    }
    __syncthreads();
    // stage wv
    for (int i = tid; i < 64*64; i += 256) s_w[i] = wv[i];
    __syncthreads();

    // pass B: v (64 cols); 256 tiles of 4x8, 1/thread
    {
        int rg = tid & 31, cg = tid >> 5;
        int r0 = rg*4, c0 = cg*8;
        uint64_t acc[4][4];
        #pragma unroll
        for (int j = 0; j < 4; j++) { uint64_t b = pack2(s_c[256+c0+2*j], s_c[256+c0+2*j+1]);
            #pragma unroll
            for (int i = 0; i < 4; i++) acc[i][j] = b; }
        gemm_48p<64,128,64>(s_xT, s_w, r0, c0, acc);
        #pragma unroll
        for (int i = 0; i < 4; i++) {
            int nn = t0 + r0 + i;
            float o[8];
            unpack2(acc[i][0], o[0], o[1]);
            unpack2(acc[i][1], o[2], o[3]);
            unpack2(acc[i][2], o[4], o[5]);
            unpack2(acc[i][3], o[6], o[7]);
            *(float4*)(g_v + (size_t)nn*DM + c0)     = make_float4(o[0],o[1],o[2],o[3]);
            *(float4*)(g_v + (size_t)nn*DM + c0 + 4) = make_float4(o[4],o[5],o[6],o[7]);
        }
    }
}

// ================= Kernel 2: kv-state reduction (deterministic) =================
__global__ __launch_bounds__(256) void k_kvred() {
    __shared__ float s_red[8][72];
    int bh = blockIdx.x / SPLIT, chunk = blockIdx.x % SPLIT;
    int b = bh >> 3, h = bh & 7;
    int tid = threadIdx.x, wid = tid >> 5, lane = tid & 31;
    float kv[8][8] = {}; float ks[8] = {};
    int s0 = chunk * (SS / SPLIT);
    for (int s = s0 + tid; s < s0 + SS/SPLIT; s += 256) {
        int base = (b*SS + s)*DM + h*8;
        float4 p0 = *(const float4*)(g_pk + base), p1 = *(const float4*)(g_pk + base + 4);
        float4 v0 = *(const float4*)(g_v  + base), v1 = *(const float4*)(g_v  + base + 4);
        float pk[8] = {p0.x,p0.y,p0.z,p0.w,p1.x,p1.y,p1.z,p1.w};
        float vvv[8] = {v0.x,v0.y,v0.z,v0.w,v1.x,v1.y,v1.z,v1.w};
        #pragma unroll
        for (int d = 0; d < 8; d++) {
            ks[d] += pk[d];
            #pragma unroll
            for (int e = 0; e < 8; e++) kv[d][e] += pk[d]*vvv[e];
        }
    }
    #pragma unroll
    for (int o = 16; o > 0; o >>= 1) {
        #pragma unroll
        for (int d = 0; d < 8; d++) {
            ks[d] += __shfl_down_sync(0xffffffffu, ks[d], o);
            #pragma unroll
            for (int e = 0; e < 8; e++)
                kv[d][e] += __shfl_down_sync(0xffffffffu, kv[d][e], o);
        }
    }
    if (lane == 0) {
        #pragma unroll
        for (int d = 0; d < 8; d++) {
            #pragma unroll
            for (int e = 0; e < 8; e++) s_red[wid][d*8+e] = kv[d][e];
            s_red[wid][64+d] = ks[d];
        }
    }
    __syncthreads();
    if (tid < 72) {
        float acc = 0.f;
        #pragma unroll
        for (int w = 0; w < 8; w++) acc += s_red[w][tid];
        g_kvp[(size_t)blockIdx.x*72 + tid] = acc;
    }
}

// ================= Kernel 3: kv-combine + attention readout + @wo + residual =================
// 128 tokens/block (unchanged — register-limited at 50% occ)
__global__ __launch_bounds__(256) void k_att(
    const float* __restrict__ wo, const float* __restrict__ bo)
{
    extern __shared__ float sm[];
    float* s_attT = sm;               // [64][128]
    float* s_w    = sm + 64*128;      // wo [64][64]
    float* s_kv   = s_w + 64*64;      // 512
    float* s_ks   = s_kv + 512;       // 64
    float* s_bo   = s_ks + 64;        // 64
    const int tid = threadIdx.x;
    const int t0 = blockIdx.x * 128;
    const int b = t0 >> 12;           // t0 / SS

    for (int i = tid; i < 64*64; i += 256) s_w[i] = wo[i];
    // fused kv-combine
    for (int i = tid; i < NH*72; i += 256) {
        int h = i / 72, idx = i % 72;
        float acc = 0.f;
        #pragma unroll
        for (int c = 0; c < SPLIT; c++)
            acc += g_kvp[(size_t)((b*NH + h)*SPLIT + c)*72 + idx];
        if (idx < 64) s_kv[h*64 + idx] = acc;
        else          s_ks[h*8 + idx - 64] = acc;
    }
    if (tid < 64) s_bo[tid] = bo[tid];

    const int r = tid >> 1, g = tid & 1;
    const int n = t0 + r;
    float p[32];
    {
        const float4* src = (const float4*)(g_pq + (size_t)n*DM + g*32);
        #pragma unroll
        for (int q = 0; q < 8; q++) {
            float4 v = src[q];
            p[q*4+0]=v.x; p[q*4+1]=v.y; p[q*4+2]=v.z; p[q*4+3]=v.w;
        }
    }
    __syncthreads();

    #pragma unroll
    for (int u = 0; u < 4; u++) {
        int h = g*4 + u;
        float den = 0.f;
        #pragma unroll
        for (int d = 0; d < 8; d++) den += p[u*8+d] * s_ks[h*8+d];
        float inv = 1.f / (den + 1e-6f);
        const float* kvb = s_kv + h*64;
        #pragma unroll
        for (int e = 0; e < 8; e++) {
            float num = 0.f;
            #pragma unroll
            for (int d = 0; d < 8; d++) num += p[u*8+d] * kvb[d*8+e];
            s_attT[(g*32 + u*8 + e)*128 + r] = num * inv;
        }
    }
    __syncthreads();

    {
        int rg = tid & 31, cg = tid >> 5;
        int r0 = rg*4, c0 = cg*8;
        uint64_t acc[4][4];
        #pragma unroll
        for (int j = 0; j < 4; j++) { uint64_t bb = pack2(s_bo[c0+2*j], s_bo[c0+2*j+1]);
            #pragma unroll
            for (int i = 0; i < 4; i++) acc[i][j] = bb; }
        gemm_48p<64,128,64>(s_attT, s_w, r0, c0, acc);
        #pragma unroll
        for (int i = 0; i < 4; i++) {
            float o[8];
            unpack2(acc[i][0], o[0], o[1]);
            unpack2(acc[i][1], o[2], o[3]);
            unpack2(acc[i][2], o[4], o[5]);
            unpack2(acc[i][3], o[6], o[7]);
            float4* ph = (float4*)(g_hh + (size_t)(t0+r0+i)*DM + c0);
            float4 h0 = ph[0], h1 = ph[1];
            h0.x += o[0]; h0.y += o[1]; h0.z += o[2]; h0.w += o[3];
            h1.x += o[4]; h1.y += o[5]; h1.z += o[6]; h1.w += o[7];
            ph[0] = h0; ph[1] = h1;
        }
    }
}

// ================= Kernel 4: fused LN2 + FFN chunked (up,gelu,down-accum) + residual =================
// 64 tokens/block; FF dim in 4 chunks of 64; down accumulates in registers.
// smem ~50 KB -> 4 blocks/SM (50% occ)
__global__ __launch_bounds__(256, 4) void k_ffn(
    const float* __restrict__ ls, const float* __restrict__ lb,
    const float* __restrict__ w1, const float* __restrict__ b1,
    const float* __restrict__ w2, const float* __restrict__ b2)
{
    extern __shared__ float sm[];
    float* s_yT  = sm;                 // [64k][64t]
    float* s_t1c = sm + 64*64;         // [64ff][64t] chunk
    float* s_w   = sm + 2*64*64;       // [64][64] staging (w1 chunk / w2 chunk)
    float* s_c   = s_w + 64*64;        // ls 64 | lb 64 | b1 256 | b2 64 = 448
    const int tid = threadIdx.x;
    const int t0 = blockIdx.x * 64;
    const int rg = tid & 15, cg = tid >> 4;
    const int r0 = rg*4, c0 = cg*4;

    for (int i = tid; i < 448; i += 256) {
        float v;
        if      (i < 64)  v = ls[i];
        else if (i < 128) v = lb[i-64];
        else if (i < 384) v = b1[i-128];
        else              v = b2[i-384];
        s_c[i] = v;
    }

    // LN2 in registers (4 threads / row, 16 cols each)
    const int r = tid >> 2, g = tid & 3;
    const int n = t0 + r;
    float4 vv[4];
    {
        const float4* src = (const float4*)(g_hh + (size_t)n*DM + g*16);
        #pragma unroll
        for (int q = 0; q < 4; q++) vv[q] = src[q];
    }
    float sum = 0.f, sq = 0.f;
    #pragma unroll
    for (int q = 0; q < 4; q++) {
        sum += vv[q].x+vv[q].y+vv[q].z+vv[q].w;
        sq  += vv[q].x*vv[q].x+vv[q].y*vv[q].y+vv[q].z*vv[q].z+vv[q].w*vv[q].w;
    }
    sum += __shfl_xor_sync(0xffffffffu, sum, 1);
    sq  += __shfl_xor_sync(0xffffffffu, sq , 1);
    sum += __shfl_xor_sync(0xffffffffu, sum, 2);
    sq  += __shfl_xor_sync(0xffffffffu, sq , 2);
    float mean = sum * (1.f/64.f);
    float rstd = rsqrtf(sq * (1.f/64.f) - mean*mean + 1e-5f);
    __syncthreads();   // s_c staged

    #pragma unroll
    for (int q = 0; q < 4; q++) {
        float vals[4] = {vv[q].x,vv[q].y,vv[q].z,vv[q].w};
        #pragma unroll
        for (int j = 0; j < 4; j++) {
            int c = g*16 + q*4 + j;
            s_yT[c*64 + r] = (vals[j]-mean)*rstd*s_c[c] + s_c[64+c];
        }
    }

    // persistent down accumulator (tokens r0.., dm cols c0..)
    uint64_t accD[4][2];
    #pragma unroll
    for (int j = 0; j < 2; j++) { uint64_t bb = pack2(s_c[384+c0+2*j], s_c[384+c0+2*j+1]);
        #pragma unroll
        for (int i = 0; i < 4; i++) accD[i][j] = bb; }

    for (int c = 0; c < 4; c++) {
        __syncthreads();   // yT ready (iter 0) / prior s_w + t1c reads done
        for (int i = tid; i < 4096; i += 256) {
            int k = i >> 6, j = i & 63;
            s_w[i] = w1[k*FFD + c*64 + j];
        }
        __syncthreads();
        // up chunk GEMM (4x4 tiles, 64 tok x 64 ff)
        uint64_t accU[4][2];
        #pragma unroll
        for (int j = 0; j < 2; j++) { uint64_t bb = pack2(s_c[128 + c*64 + c0+2*j], s_c[128 + c*64 + c0+2*j+1]);
            #pragma unroll
            for (int i = 0; i < 4; i++) accU[i][j] = bb; }
        gemm_44p<64,64,64>(s_yT, s_w, r0, c0, accU);
        #pragma unroll
        for (int i = 0; i < 4; i++) {
            float o0,o1,o2,o3;
            unpack2(accU[i][0], o0, o1);
            unpack2(accU[i][1], o2, o3);
            s_t1c[(c0+0)*64 + r0+i] = gelu_f(o0);
            s_t1c[(c0+1)*64 + r0+i] = gelu_f(o1);
            s_t1c[(c0+2)*64 + r0+i] = gelu_f(o2);
            s_t1c[(c0+3)*64 + r0+i] = gelu_f(o3);
        }
        __syncthreads();   // t1c written; s_w free for restage
        for (int i = tid; i < 4096; i += 256) {
            int k = i >> 6, j = i & 63;
            s_w[i] = w2[(size_t)(c*64 + k)*DM + j];
        }
        __syncthreads();
        gemm_44p<64,64,64>(s_t1c, s_w, r0, c0, accD);
    }

    // epilogue: hh += accD (bias already folded)
    #pragma unroll
    for (int i = 0; i < 4; i++) {
        float o0,o1,o2,o3;
        unpack2(accD[i][0], o0, o1);
        unpack2(accD[i][1], o2, o3);
        float4* ph = (float4*)(g_hh + (size_t)(t0+r0+i)*DM + c0);
        float4 h0 = *ph;
        h0.x += o0; h0.y += o1; h0.z += o2; h0.w += o3;
        *ph = h0;
    }
}

// ================= Kernel 5: final LN + mask + output GEMM =================
// 128 tokens/block x 128-col chunks -> smem 65 KB -> 3 blocks/SM
__global__ __launch_bounds__(256, 3) void k_out(
    const float* __restrict__ mask,
    const float* __restrict__ ls, const float* __restrict__ lb,
    const float* __restrict__ w_out, const float* __restrict__ b_out,
    float* __restrict__ out)
{
    extern __shared__ float sm[];
    float* s_xT = sm;               // [64][128]
    float* s_w  = sm + 64*128;      // [64][128] chunk
    float* s_c  = s_w + 64*128;     // ls 64 | lb 64 | bias 128
    const int tid = threadIdx.x;
    const int t0 = blockIdx.x * 128;
    const int c00 = blockIdx.y * 128;

    for (int i = tid; i < 256; i += 256) {
        float v;
        if      (i < 64)  v = ls[i];
        else if (i < 128) v = lb[i-64];
        else { int c = c00 + i - 128; v = (c < CC) ? b_out[c] : 0.f; }
        s_c[i] = v;
    }
    for (int i = tid; i < 64*128; i += 256) {
        int k = i >> 7, j = i & 127;
        int c = c00 + j;
        s_w[i] = (c < CC) ? w_out[(size_t)k*CC + c] : 0.f;
    }

    // final LN (+mask) in registers (2 threads / row, 32 cols each)
    const int r = tid >> 1, g = tid & 1;
    const int n = t0 + r;
    float4 vv[8];
    {
        const float4* src = (const float4*)(g_hh + (size_t)n*DM + g*32);
        #pragma unroll
        for (int q = 0; q < 8; q++) vv[q] = src[q];
    }
    float sum = 0.f, sq = 0.f;
    #pragma unroll
    for (int q = 0; q < 8; q++) {
        sum += vv[q].x+vv[q].y+vv[q].z+vv[q].w;
        sq  += vv[q].x*vv[q].x+vv[q].y*vv[q].y+vv[q].z*vv[q].z+vv[q].w*vv[q].w;
    }
    sum += __shfl_xor_sync(0xffffffffu, sum, 1);
    sq  += __shfl_xor_sync(0xffffffffu, sq , 1);
    float mean = sum * (1.f/64.f);
    float rstd = rsqrtf(sq * (1.f/64.f) - mean*mean + 1e-5f);
    float m = mask[n];
    __syncthreads();

    #pragma unroll
    for (int q = 0; q < 8; q++) {
        float vals[4] = {vv[q].x,vv[q].y,vv[q].z,vv[q].w};
        #pragma unroll
        for (int j = 0; j < 4; j++) {
            int c = g*32 + q*4 + j;
            s_xT[c*128 + r] = ((vals[j]-mean)*rstd*s_c[c] + s_c[64+c]) * m;
        }
    }
    __syncthreads();

    // GEMM: 128 tok x 128 cols = 512 tiles (4x8), 2/thread
    for (int t = tid; t < 512; t += 256) {
        int rg = t & 31, cg = t >> 5;
        int r0 = rg*4, c0 = cg*8;
        uint64_t acc[4][4];
        #pragma unroll
        for (int j = 0; j < 4; j++) { uint64_t bb = pack2(s_c[128+c0+2*j], s_c[128+c0+2*j+1]);
            #pragma unroll
            for (int i = 0; i < 4; i++) acc[i][j] = bb; }
        gemm_48p<64,128,128>(s_xT, s_w, r0, c0, acc);
        #pragma unroll
        for (int i = 0; i < 4; i++) {
            float o[8];
            unpack2(acc[i][0], o[0], o[1]);
            unpack2(acc[i][1], o[2], o[3]);
            unpack2(acc[i][2], o[4], o[5]);
            unpack2(acc[i][3], o[6], o[7]);
            size_t ob = (size_t)(t0+r0+i)*CC + c00 + c0;
            #pragma unroll
            for (int j = 0; j < 8; j++)
                if (c00 + c0 + j < CC) out[ob + j] = o[j];
        }
    }
}

extern "C" void kernel_launch(void* const* d_in, const int* in_sizes, int n_in,
                              void* d_out, int out_size) {
    const float* ex    = (const float*)d_in[0];
    const int*   labels= (const int*)  d_in[1];
    const float* mask  = (const float*)d_in[2];
    const float* we    = (const float*)d_in[3];
    const float* be    = (const float*)d_in[4];
    const float* lemb  = (const float*)d_in[5];
    const float* w_in  = (const float*)d_in[6];
    const float* b_in  = (const float*)d_in[7];
    const float* ln1_s = (const float*)d_in[8];
    const float* ln1_b = (const float*)d_in[9];
    const float* wq    = (const float*)d_in[10];
    const float* bq    = (const float*)d_in[11];
    const float* wk    = (const float*)d_in[12];
    const float* bk    = (const float*)d_in[13];
    const float* wv    = (const float*)d_in[14];
    const float* bv    = (const float*)d_in[15];
    const float* wo    = (const float*)d_in[16];
    const float* bo    = (const float*)d_in[17];
    const float* ln2_s = (const float*)d_in[18];
    const float* ln2_b = (const float*)d_in[19];
    const float* w1    = (const float*)d_in[20];
    const float* b1    = (const float*)d_in[21];
    const float* w2    = (const float*)d_in[22];
    const float* b2    = (const float*)d_in[23];
    const float* lnf_s = (const float*)d_in[24];
    const float* lnf_b = (const float*)d_in[25];
    const float* w_out = (const float*)d_in[26];
    const float* b_out = (const float*)d_in[27];
    float* out = (float*)d_out;

    const int smem_embed = (2*128*68 + 128*64 + 192) * 4;
    const int smem_qkv   = (64*128 + 64*128 + 320) * 4;
    const int smem_att   = (64*128 + 64*64 + 512 + 64 + 64) * 4;
    const int smem_ffn   = (3*64*64 + 448) * 4;
    const int smem_out   = (64*128 + 64*128 + 256) * 4;

    cudaFuncSetAttribute(k_embed, cudaFuncAttributeMaxDynamicSharedMemorySize, smem_embed);
    cudaFuncSetAttribute(k_qkv,   cudaFuncAttributeMaxDynamicSharedMemorySize, smem_qkv);
    cudaFuncSetAttribute(k_att,   cudaFuncAttributeMaxDynamicSharedMemorySize, smem_att);
    cudaFuncSetAttribute(k_ffn,   cudaFuncAttributeMaxDynamicSharedMemorySize, smem_ffn);
    cudaFuncSetAttribute(k_out,   cudaFuncAttributeMaxDynamicSharedMemorySize, smem_out);

    k_embed<<<NTOK/64, 256, smem_embed>>>(ex, labels, we, be, lemb, w_in, b_in);
    for (int i = 0; i < NL; i++) {
        k_qkv<<<NTOK/128, 256, smem_qkv>>>(mask, ln1_s + i*DM, ln1_b + i*DM,
                                wq + i*DM*DM, bq + i*DM,
                                wk + i*DM*DM, bk + i*DM,
                                wv + i*DM*DM, bv + i*DM);
        k_kvred<<<NB*NH*SPLIT, 256>>>();
        k_att<<<NTOK/128, 256, smem_att>>>(wo + i*DM*DM, bo + i*DM);
        k_ffn<<<NTOK/64, 256, smem_ffn>>>(ln2_s + i*DM, ln2_b + i*DM,
                                 w1 + i*DM*FFD, b1 + i*FFD,
                                 w2 + i*FFD*DM, b2 + i*DM);
    }
    dim3 og(NTOK/128, (CC + 127)/128);
    k_out<<<og, 256, smem_out>>>(mask, lnf_s, lnf_b, w_out, b_out, out);
}